// round 6
// baseline (speedup 1.0000x reference)
#include <cuda_runtime.h>
#include <cuda_bf16.h>

// NonMaximaSuppression3d: x (B=4, C=2, D=64, H=256, W=256) fp32.
// out = x where x > max(26 edge-clamped neighbors) else 0.
//
//   t       = max(v[y-1], v[y+1])          elementwise     (vertical first!)
//   s       = hmax3(t)                     = max(ra, rc)
//   rb      = hmax3(v[y])
//   mf(d)   = max(s, rb)                   full in-plane 3x3
//   mc(d)   = max(s, max(v1[x-1],v1[x+1])) 8 in-plane nbrs, no center
//   max_nc  = max(mf(d-1), mc(d), mf(d+1)) (d clamped)
// Edge-pad == clamped indexing (boundary voxels self-compare -> suppressed).
//
// R5 lesson: occupancy is residency-limited, not grid-limited; the bind is
// per-thread MLP. This version runs a 2-deep load pipeline (loads for plane
// d+2 in flight while computing stats of d+1 and storing d) -> ~6 outstanding
// LDG.128 per thread instead of 3.

#define D_DIM 64
#define H_DIM 256
#define W_DIM 256
#define HW    (H_DIM * W_DIM)
#define W4    (W_DIM / 4)
#define CHUNK 32
#define NCHUNK (D_DIM / CHUNK)   // 2
#define FULL  0xffffffffu

struct Raw {
    float4 v0, v1, v2;          // rows y-1, y, y+1 (clamped), 4-wide segment
    float  l0, l1, l2;          // left halo scalars (valid in lane 0)
    float  r0, r1, r2;          // right halo scalars (valid in lane 31)
};

__device__ __forceinline__ void load_plane(const float* __restrict__ pbase,
                                           int ym, int y, int yp,
                                           int x4, int lane, Raw& rw)
{
    const float* __restrict__ r0 = pbase + ym * W_DIM;
    const float* __restrict__ r1 = pbase + y  * W_DIM;
    const float* __restrict__ r2 = pbase + yp * W_DIM;

    rw.v0 = *((const float4*)r0 + x4);
    rw.v1 = *((const float4*)r1 + x4);
    rw.v2 = *((const float4*)r2 + x4);

    if (lane == 0) {
        const int li = (x4 == 0) ? 0 : 4 * x4 - 1;      // clamp == self at x edge
        rw.l0 = r0[li]; rw.l1 = r1[li]; rw.l2 = r2[li];
    }
    if (lane == 31) {
        const int ri = (x4 == W4 - 1) ? (W_DIM - 1) : 4 * x4 + 4;
        rw.r0 = r0[ri]; rw.r1 = r1[ri]; rw.r2 = r2[ri];
    }
}

__device__ __forceinline__ void compute_stats(const Raw& rw, int lane,
                                              float4& xc, float4& mc, float4& mf)
{
    // vertical max of top/bottom rows
    float4 t;
    t.x = fmaxf(rw.v0.x, rw.v2.x);
    t.y = fmaxf(rw.v0.y, rw.v2.y);
    t.z = fmaxf(rw.v0.z, rw.v2.z);
    t.w = fmaxf(rw.v0.w, rw.v2.w);

    float Lt_s = __shfl_up_sync(FULL,   t.w, 1);
    float Rt_s = __shfl_down_sync(FULL, t.x, 1);
    float Lc_s = __shfl_up_sync(FULL,   rw.v1.w, 1);
    float Rc_s = __shfl_down_sync(FULL, rw.v1.x, 1);

    float Lt = (lane == 0)  ? fmaxf(rw.l0, rw.l2) : Lt_s;
    float Rt = (lane == 31) ? fmaxf(rw.r0, rw.r2) : Rt_s;
    float Lc = (lane == 0)  ? rw.l1 : Lc_s;
    float Rc = (lane == 31) ? rw.r1 : Rc_s;

    float4 s;   // horizontal 3-max of t == max(ra, rc)
    s.x = fmaxf(fmaxf(Lt,  t.x), t.y);
    s.y = fmaxf(fmaxf(t.x, t.y), t.z);
    s.z = fmaxf(fmaxf(t.y, t.z), t.w);
    s.w = fmaxf(fmaxf(t.z, t.w), Rt);

    float4 rb;  // horizontal 3-max of center row
    rb.x = fmaxf(fmaxf(Lc,      rw.v1.x), rw.v1.y);
    rb.y = fmaxf(fmaxf(rw.v1.x, rw.v1.y), rw.v1.z);
    rb.z = fmaxf(fmaxf(rw.v1.y, rw.v1.z), rw.v1.w);
    rb.w = fmaxf(fmaxf(rw.v1.z, rw.v1.w), Rc);

    float4 lr;  // left/right of center row, excluding center
    lr.x = fmaxf(Lc,      rw.v1.y);
    lr.y = fmaxf(rw.v1.x, rw.v1.z);
    lr.z = fmaxf(rw.v1.y, rw.v1.w);
    lr.w = fmaxf(rw.v1.z, Rc);

    mf.x = fmaxf(s.x, rb.x);
    mf.y = fmaxf(s.y, rb.y);
    mf.z = fmaxf(s.z, rb.z);
    mf.w = fmaxf(s.w, rb.w);

    mc.x = fmaxf(s.x, lr.x);
    mc.y = fmaxf(s.y, lr.y);
    mc.z = fmaxf(s.z, lr.z);
    mc.w = fmaxf(s.w, lr.w);

    xc = rw.v1;
}

__global__ __launch_bounds__(256, 3)
void nms3d_kernel(const float* __restrict__ in, float* __restrict__ out)
{
    const int tid  = blockIdx.x * blockDim.x + threadIdx.x;
    const int lane = threadIdx.x & 31;

    const int x4    = tid & (W4 - 1);
    const int y     = (tid >> 6) & (H_DIM - 1);
    const int rest  = tid >> 14;
    const int chunk = rest & (NCHUNK - 1);
    const int bc    = rest >> 1;               // NCHUNK == 2

    const int d0 = chunk * CHUNK;

    const float* __restrict__ base  = in  + (size_t)bc * D_DIM * HW;
    float*       __restrict__ obase = out + (size_t)bc * D_DIM * HW;

    const int ym = (y > 0)         ? y - 1 : 0;
    const int yp = (y < H_DIM - 1) ? y + 1 : H_DIM - 1;

    Raw rw_n, rw_nn;
    float4 xc, mc, mf, mf_prev;

    if (d0 == 0) {
        Raw rw0;
        load_plane(base,      ym, y, yp, x4, lane, rw0);
        load_plane(base + HW, ym, y, yp, x4, lane, rw_n);     // plane 1
        compute_stats(rw0, lane, xc, mc, mf);
        mf_prev = mf;                                         // d-1 clamps to 0
    } else {
        Raw rwm, rw0;
        load_plane(base + (size_t)(d0 - 1) * HW, ym, y, yp, x4, lane, rwm);
        load_plane(base + (size_t)d0       * HW, ym, y, yp, x4, lane, rw0);
        load_plane(base + (size_t)(d0 + 1) * HW, ym, y, yp, x4, lane, rw_n);
        float4 txc, tmc;
        compute_stats(rwm, lane, txc, tmc, mf_prev);
        compute_stats(rw0, lane, xc, mc, mf);
    }

    #pragma unroll 2
    for (int d = d0; d < d0 + CHUNK; ++d) {
        // issue loads for plane d+2 (consumed next iteration)
        const int dnn = d + 2;
        if (dnn < D_DIM && dnn <= d0 + CHUNK) {
            load_plane(base + (size_t)dnn * HW, ym, y, yp, x4, lane, rw_nn);
        }

        // stats of plane d+1 from loads issued last iteration
        float4 xcn, mcn, mfn;
        if (d < D_DIM - 1) {
            compute_stats(rw_n, lane, xcn, mcn, mfn);
        } else {
            xcn = xc; mcn = mc; mfn = mf;       // d+1 clamps to last plane
        }

        float4 m, o;
        m.x = fmaxf(fmaxf(mf_prev.x, mc.x), mfn.x);
        m.y = fmaxf(fmaxf(mf_prev.y, mc.y), mfn.y);
        m.z = fmaxf(fmaxf(mf_prev.z, mc.z), mfn.z);
        m.w = fmaxf(fmaxf(mf_prev.w, mc.w), mfn.w);

        o.x = (xc.x > m.x) ? xc.x : 0.0f;
        o.y = (xc.y > m.y) ? xc.y : 0.0f;
        o.z = (xc.z > m.z) ? xc.z : 0.0f;
        o.w = (xc.w > m.w) ? xc.w : 0.0f;

        // streaming store: output is never re-read, keep input resident in L2
        __stcs((float4*)(obase + (size_t)d * HW + y * W_DIM) + x4, o);

        mf_prev = mf;
        xc = xcn; mc = mcn; mf = mfn;
        rw_n = rw_nn;
    }
}

extern "C" void kernel_launch(void* const* d_in, const int* in_sizes, int n_in,
                              void* d_out, int out_size)
{
    const float* x   = (const float*)d_in[0];
    float*       out = (float*)d_out;

    const int n  = in_sizes[0];
    const int bc = n / (D_DIM * HW);               // = 8 for the reference shape

    const int total   = bc * H_DIM * W4 * NCHUNK;  // thread per (bc,y,x4,chunk)
    const int threads = 256;
    const int blocks  = total / threads;           // 1024 for the reference shape

    nms3d_kernel<<<blocks, threads>>>(x, out);
}

// round 7
// speedup vs baseline: 2.1261x; 2.1261x over previous
#include <cuda_runtime.h>
#include <cuda_bf16.h>

// NonMaximaSuppression3d: x (B=4, C=2, D=64, H=256, W=256) fp32.
// out = x where x > max(26 edge-clamped neighbors) else 0.
//
//   t       = max(v[y-1], v[y+1])          elementwise (vertical first)
//   s       = hmax3(t)
//   rb      = hmax3(v[y])
//   mf(d)   = max(s, rb)                   full in-plane 3x3
//   mc(d)   = max(s, max(v1[x-1],v1[x+1])) 8 in-plane nbrs, no center
//   max_nc  = max(mf(d-1), mc(d), mf(d+1)) (d clamped)
// Edge-pad == clamped indexing (boundary voxels self-compare -> suppressed).
//
// R6 lesson: register pipelines spill (L1 2.6x from local traffic). This round
// hides DRAM latency with prefetch.global.L2 of the thread's own row 3 planes
// ahead (no registers held, 1 extra wavefront/step); halo rows are covered by
// the neighboring-y warps' own prefetches. Simple rolling 3-plane register
// window otherwise (R2 structure).

#define D_DIM 64
#define H_DIM 256
#define W_DIM 256
#define HW    (H_DIM * W_DIM)
#define W4    (W_DIM / 4)
#define CHUNK 32
#define NCHUNK (D_DIM / CHUNK)   // 2
#define PFDIST 3
#define FULL  0xffffffffu

__device__ __forceinline__ void plane_stats(const float* __restrict__ pbase,
                                            int ym, int y, int yp,
                                            int x4, int lane,
                                            float4& xc, float4& mc, float4& mf)
{
    const float* __restrict__ r0 = pbase + ym * W_DIM;
    const float* __restrict__ r1 = pbase + y  * W_DIM;
    const float* __restrict__ r2 = pbase + yp * W_DIM;

    float4 v0 = *((const float4*)r0 + x4);
    float4 v1 = *((const float4*)r1 + x4);
    float4 v2 = *((const float4*)r2 + x4);

    // edge-lane halo scalars (predicated; 1 wavefront each)
    float l0, l1, l2, h0, h1, h2;
    if (lane == 0) {
        const int li = (x4 == 0) ? 0 : 4 * x4 - 1;      // clamp == self at x edge
        l0 = r0[li]; l1 = r1[li]; l2 = r2[li];
    }
    if (lane == 31) {
        const int ri = (x4 == W4 - 1) ? (W_DIM - 1) : 4 * x4 + 4;
        h0 = r0[ri]; h1 = r1[ri]; h2 = r2[ri];
    }

    // vertical max of top/bottom rows first (saves shuffles + ops)
    float4 t;
    t.x = fmaxf(v0.x, v2.x);
    t.y = fmaxf(v0.y, v2.y);
    t.z = fmaxf(v0.z, v2.z);
    t.w = fmaxf(v0.w, v2.w);

    float Lt_s = __shfl_up_sync(FULL,   t.w, 1);
    float Rt_s = __shfl_down_sync(FULL, t.x, 1);
    float Lc_s = __shfl_up_sync(FULL,   v1.w, 1);
    float Rc_s = __shfl_down_sync(FULL, v1.x, 1);

    float Lt = (lane == 0)  ? fmaxf(l0, l2) : Lt_s;
    float Rt = (lane == 31) ? fmaxf(h0, h2) : Rt_s;
    float Lc = (lane == 0)  ? l1 : Lc_s;
    float Rc = (lane == 31) ? h1 : Rc_s;

    float4 s;   // horizontal 3-max of t == max over rows y-1,y+1 of 3x3 window
    s.x = fmaxf(fmaxf(Lt,  t.x), t.y);
    s.y = fmaxf(fmaxf(t.x, t.y), t.z);
    s.z = fmaxf(fmaxf(t.y, t.z), t.w);
    s.w = fmaxf(fmaxf(t.z, t.w), Rt);

    float4 rb;  // horizontal 3-max of center row
    rb.x = fmaxf(fmaxf(Lc,   v1.x), v1.y);
    rb.y = fmaxf(fmaxf(v1.x, v1.y), v1.z);
    rb.z = fmaxf(fmaxf(v1.y, v1.z), v1.w);
    rb.w = fmaxf(fmaxf(v1.z, v1.w), Rc);

    float4 lr;  // left/right of center row, excluding center
    lr.x = fmaxf(Lc,   v1.y);
    lr.y = fmaxf(v1.x, v1.z);
    lr.z = fmaxf(v1.y, v1.w);
    lr.w = fmaxf(v1.z, Rc);

    mf.x = fmaxf(s.x, rb.x);
    mf.y = fmaxf(s.y, rb.y);
    mf.z = fmaxf(s.z, rb.z);
    mf.w = fmaxf(s.w, rb.w);

    mc.x = fmaxf(s.x, lr.x);
    mc.y = fmaxf(s.y, lr.y);
    mc.z = fmaxf(s.z, lr.z);
    mc.w = fmaxf(s.w, lr.w);

    xc = v1;
}

__global__ __launch_bounds__(256)
void nms3d_kernel(const float* __restrict__ in, float* __restrict__ out)
{
    const int tid  = blockIdx.x * blockDim.x + threadIdx.x;
    const int lane = threadIdx.x & 31;

    const int x4    = tid & (W4 - 1);
    const int y     = (tid >> 6) & (H_DIM - 1);
    const int rest  = tid >> 14;
    const int chunk = rest & (NCHUNK - 1);
    const int bc    = rest >> 1;               // NCHUNK == 2

    const int d0 = chunk * CHUNK;

    const float* __restrict__ base  = in  + (size_t)bc * D_DIM * HW;
    float*       __restrict__ obase = out + (size_t)bc * D_DIM * HW;

    const int ym = (y > 0)         ? y - 1 : 0;
    const int yp = (y < H_DIM - 1) ? y + 1 : H_DIM - 1;

    // warm the L2 for the first few planes of this chunk (own row only;
    // halo rows arrive via the neighboring-y threads' prefetches)
    if ((lane & 7) == 0) {
        const float* p0 = base + (size_t)d0 * HW + y * W_DIM + 4 * x4;
        #pragma unroll
        for (int k = 0; k < PFDIST; ++k) {
            if (d0 + k < D_DIM)
                asm volatile("prefetch.global.L2 [%0];" :: "l"(p0 + (size_t)k * HW));
        }
    }

    float4 xc, mc, mf, mf_prev;
    if (d0 == 0) {
        plane_stats(base, ym, y, yp, x4, lane, xc, mc, mf);
        mf_prev = mf;                           // d-1 clamps to plane 0
    } else {
        float4 txc, tmc;
        plane_stats(base + (size_t)(d0 - 1) * HW, ym, y, yp, x4, lane,
                    txc, tmc, mf_prev);
        plane_stats(base + (size_t)d0 * HW, ym, y, yp, x4, lane, xc, mc, mf);
    }

    #pragma unroll 1
    for (int d = d0; d < d0 + CHUNK; ++d) {
        // prefetch own row of plane d+PFDIST into L2 (registers-free latency hiding)
        if ((lane & 7) == 0 && d + PFDIST < D_DIM) {
            const float* pf = base + (size_t)(d + PFDIST) * HW + y * W_DIM + 4 * x4;
            asm volatile("prefetch.global.L2 [%0];" :: "l"(pf));
        }

        float4 xcn, mcn, mfn;
        if (d < D_DIM - 1) {
            plane_stats(base + (size_t)(d + 1) * HW, ym, y, yp, x4, lane,
                        xcn, mcn, mfn);
        } else {
            xcn = xc; mcn = mc; mfn = mf;       // d+1 clamps to last plane
        }

        float4 m, o;
        m.x = fmaxf(fmaxf(mf_prev.x, mc.x), mfn.x);
        m.y = fmaxf(fmaxf(mf_prev.y, mc.y), mfn.y);
        m.z = fmaxf(fmaxf(mf_prev.z, mc.z), mfn.z);
        m.w = fmaxf(fmaxf(mf_prev.w, mc.w), mfn.w);

        o.x = (xc.x > m.x) ? xc.x : 0.0f;
        o.y = (xc.y > m.y) ? xc.y : 0.0f;
        o.z = (xc.z > m.z) ? xc.z : 0.0f;
        o.w = (xc.w > m.w) ? xc.w : 0.0f;

        // streaming store: output is never re-read, keep input resident in L2
        __stcs((float4*)(obase + (size_t)d * HW + y * W_DIM) + x4, o);

        mf_prev = mf;
        xc = xcn; mc = mcn; mf = mfn;
    }
}

extern "C" void kernel_launch(void* const* d_in, const int* in_sizes, int n_in,
                              void* d_out, int out_size)
{
    const float* x   = (const float*)d_in[0];
    float*       out = (float*)d_out;

    const int n  = in_sizes[0];
    const int bc = n / (D_DIM * HW);               // = 8 for the reference shape

    const int total   = bc * H_DIM * W4 * NCHUNK;  // thread per (bc,y,x4,chunk)
    const int threads = 256;
    const int blocks  = total / threads;           // 1024 for the reference shape

    nms3d_kernel<<<blocks, threads>>>(x, out);
}

// round 12
// speedup vs baseline: 2.4813x; 1.1671x over previous
#include <cuda_runtime.h>
#include <cuda_bf16.h>

// NonMaximaSuppression3d: x (B=4, C=2, D=64, H=256, W=256) fp32.
// out = x where x > max(26 edge-clamped neighbors) else 0.
//
//   t       = max(v[y-1], v[y+1])          elementwise (vertical first)
//   s       = hmax3(t)
//   rb      = hmax3(v[y])
//   mf(d)   = max(s, rb)                   full in-plane 3x3
//   mc(d)   = max(s, max(v1[x-1],v1[x+1])) 8 in-plane nbrs, no center
//   max_nc  = max(mf(d-1), mc(d), mf(d+1)) (d clamped)
// Edge-pad == clamped indexing. mf of a clamped plane includes the center
// voxel itself, so face planes (d=0, d=D-1) are entirely suppressed — the
// reference's exact semantics; lets the d-march be fully branchless.
//
// R7 WIN (79.8 -> 61.9us): L2 prefetch 3 planes ahead converts first-touch
// DRAM latency to L2-hit latency. R8-R11 all infra failures — design still
// unmeasured; unchanged resubmit: branchless prologue/tail via d-clamping +
// pointer marching + launch_bounds(256,4) to cut regs 70 -> <=64 (4th CTA/SM).

#define D_DIM 64
#define H_DIM 256
#define W_DIM 256
#define HW    (H_DIM * W_DIM)
#define W4    (W_DIM / 4)
#define CHUNK 32
#define NCHUNK (D_DIM / CHUNK)   // 2
#define PFDIST 3
#define FULL  0xffffffffu

__device__ __forceinline__ void plane_stats(const float* __restrict__ pbase,
                                            int ym_off, int yp_off,
                                            int li_off, int ri_off, int lane,
                                            float4& xc, float4& mc, float4& mf)
{
    // pbase points at this thread's own float4 segment in the center row.
    const float* __restrict__ r0 = pbase + ym_off;   // row y-1 (clamped)
    const float* __restrict__ r1 = pbase;            // row y
    const float* __restrict__ r2 = pbase + yp_off;   // row y+1 (clamped)

    float4 v0 = *(const float4*)r0;
    float4 v1 = *(const float4*)r1;
    float4 v2 = *(const float4*)r2;

    // edge-lane halo scalars (predicated; 1 wavefront each)
    float Lt_e, Lc_e, Rt_e, Rc_e;
    if (lane == 0) {
        Lt_e = fmaxf(r0[li_off], r2[li_off]);
        Lc_e = r1[li_off];
    }
    if (lane == 31) {
        Rt_e = fmaxf(r0[ri_off], r2[ri_off]);
        Rc_e = r1[ri_off];
    }

    // vertical max of top/bottom rows first
    float4 t;
    t.x = fmaxf(v0.x, v2.x);
    t.y = fmaxf(v0.y, v2.y);
    t.z = fmaxf(v0.z, v2.z);
    t.w = fmaxf(v0.w, v2.w);

    float Lt_s = __shfl_up_sync(FULL,   t.w, 1);
    float Rt_s = __shfl_down_sync(FULL, t.x, 1);
    float Lc_s = __shfl_up_sync(FULL,   v1.w, 1);
    float Rc_s = __shfl_down_sync(FULL, v1.x, 1);

    float Lt = (lane == 0)  ? Lt_e : Lt_s;
    float Rt = (lane == 31) ? Rt_e : Rt_s;
    float Lc = (lane == 0)  ? Lc_e : Lc_s;
    float Rc = (lane == 31) ? Rc_e : Rc_s;

    float4 s;   // horizontal 3-max of t
    s.x = fmaxf(fmaxf(Lt,  t.x), t.y);
    s.y = fmaxf(fmaxf(t.x, t.y), t.z);
    s.z = fmaxf(fmaxf(t.y, t.z), t.w);
    s.w = fmaxf(fmaxf(t.z, t.w), Rt);

    float4 rb;  // horizontal 3-max of center row
    rb.x = fmaxf(fmaxf(Lc,   v1.x), v1.y);
    rb.y = fmaxf(fmaxf(v1.x, v1.y), v1.z);
    rb.z = fmaxf(fmaxf(v1.y, v1.z), v1.w);
    rb.w = fmaxf(fmaxf(v1.z, v1.w), Rc);

    float4 lr;  // left/right of center row, excluding center
    lr.x = fmaxf(Lc,   v1.y);
    lr.y = fmaxf(v1.x, v1.z);
    lr.z = fmaxf(v1.y, v1.w);
    lr.w = fmaxf(v1.z, Rc);

    mf.x = fmaxf(s.x, rb.x);
    mf.y = fmaxf(s.y, rb.y);
    mf.z = fmaxf(s.z, rb.z);
    mf.w = fmaxf(s.w, rb.w);

    mc.x = fmaxf(s.x, lr.x);
    mc.y = fmaxf(s.y, lr.y);
    mc.z = fmaxf(s.z, lr.z);
    mc.w = fmaxf(s.w, lr.w);

    xc = v1;
}

__global__ __launch_bounds__(256, 4)
void nms3d_kernel(const float* __restrict__ in, float* __restrict__ out)
{
    const int tid  = blockIdx.x * blockDim.x + threadIdx.x;
    const int lane = threadIdx.x & 31;

    const int x4    = tid & (W4 - 1);
    const int y     = (tid >> 6) & (H_DIM - 1);
    const int rest  = tid >> 14;
    const int chunk = rest & (NCHUNK - 1);
    const int bc    = rest >> 1;               // NCHUNK == 2

    const int d0 = chunk * CHUNK;

    // Per-thread anchor: own float4 segment of the center row.
    const float* __restrict__ anchor =
        in + (size_t)bc * D_DIM * HW + (size_t)d0 * HW + y * W_DIM + 4 * x4;
    float* __restrict__ oanchor =
        out + (size_t)bc * D_DIM * HW + (size_t)d0 * HW + y * W_DIM + 4 * x4;

    const int ym_off = ((y > 0)         ? -W_DIM : 0);
    const int yp_off = ((y < H_DIM - 1) ?  W_DIM : 0);
    const int li_off = (x4 == 0)      ? 0 : -1;   // clamp == self at x edge
    const int ri_off = (x4 == W4 - 1) ? 3 : 4;

    // warm L2 for the first planes of this chunk (own row only; halo rows
    // arrive via the neighboring-y threads' prefetches)
    if ((lane & 7) == 0) {
        #pragma unroll
        for (int k = 0; k < PFDIST; ++k)
            if (d0 + k < D_DIM)
                asm volatile("prefetch.global.L2 [%0];" :: "l"(anchor + (size_t)k * HW));
    }

    float4 xc, mc, mf, mf_prev;
    {
        // stats of plane clamp(d0-1): for d0==0 this is plane 0 itself, whose
        // mf includes the center -> face plane suppressed (reference-exact).
        float4 txc, tmc;
        const float* prev = (d0 == 0) ? anchor : anchor - HW;
        plane_stats(prev,   ym_off, yp_off, li_off, ri_off, lane, txc, tmc, mf_prev);
        plane_stats(anchor, ym_off, yp_off, li_off, ri_off, lane, xc, mc, mf);
    }

    const float* pn = anchor + HW;      // plane d+1 (clamped at volume end)
    const int dlast = D_DIM - 1;

    #pragma unroll 1
    for (int d = d0; d < d0 + CHUNK; ++d) {
        // prefetch own row of plane d+PFDIST into L2
        if ((lane & 7) == 0 && d + PFDIST < D_DIM)
            asm volatile("prefetch.global.L2 [%0];" :: "l"(anchor + (size_t)(d - d0 + PFDIST) * HW));

        // stats of plane min(d+1, dlast); last plane recompute == current mf.
        float4 xcn, mcn, mfn;
        const float* psrc = (d < dlast) ? pn : pn - HW;
        plane_stats(psrc, ym_off, yp_off, li_off, ri_off, lane, xcn, mcn, mfn);

        float4 m, o;
        m.x = fmaxf(fmaxf(mf_prev.x, mc.x), mfn.x);
        m.y = fmaxf(fmaxf(mf_prev.y, mc.y), mfn.y);
        m.z = fmaxf(fmaxf(mf_prev.z, mc.z), mfn.z);
        m.w = fmaxf(fmaxf(mf_prev.w, mc.w), mfn.w);

        o.x = (xc.x > m.x) ? xc.x : 0.0f;
        o.y = (xc.y > m.y) ? xc.y : 0.0f;
        o.z = (xc.z > m.z) ? xc.z : 0.0f;
        o.w = (xc.w > m.w) ? xc.w : 0.0f;

        // streaming store: output never re-read, keep input resident in L2
        __stcs((float4*)oanchor, o);

        mf_prev = mf;
        xc = xcn; mc = mcn; mf = mfn;
        pn += HW;
        oanchor += HW;
    }
}

extern "C" void kernel_launch(void* const* d_in, const int* in_sizes, int n_in,
                              void* d_out, int out_size)
{
    const float* x   = (const float*)d_in[0];
    float*       out = (float*)d_out;

    const int n  = in_sizes[0];
    const int bc = n / (D_DIM * HW);               // = 8 for the reference shape

    const int total   = bc * H_DIM * W4 * NCHUNK;  // thread per (bc,y,x4,chunk)
    const int threads = 256;
    const int blocks  = total / threads;           // 1024 for the reference shape

    nms3d_kernel<<<blocks, threads>>>(x, out);
}

// round 17
// speedup vs baseline: 2.5458x; 1.0260x over previous
#include <cuda_runtime.h>
#include <cuda_bf16.h>

// NonMaximaSuppression3d: x (B=4, C=2, D=64, H=256, W=256) fp32.
// out = x where x > max(26 edge-clamped neighbors) else 0.
//
//   t   = max(v[y-1], v[y+1])      (vertical first)
//   lr  = shifted-pair max of center row (excl. center)
//   rb  = max(lr, v1)              == hmax3(center row)
//   s   = hmax3(t) via pairwise partials
//   mf  = max(s, rb); mc = max(s, lr)
//   max_nc = max(mf(d-1), mc(d), mf(d+1)), d clamped
// Edge-pad == clamped indexing; face planes self-suppress (reference-exact).
//
// R7 WIN: L2 prefetch (79.8->61.9). R12 WIN: branchless+lb(256,4) regs 64,
// occ 42%, DRAM 63% (61.9->53.1). R13-R16 infra failures — design still
// unmeasured, unchanged resubmit: unroll 2 kills ~12 rotation MOVs/step,
// lr-first/pairwise max tree (-5 ops/step), marching prefetch ptr, 128-thread
// blocks for finer wave-tail granularity. Target: alu 54->40%, DRAM 63->70%+.

#define D_DIM 64
#define H_DIM 256
#define W_DIM 256
#define HW    (H_DIM * W_DIM)
#define W4    (W_DIM / 4)
#define CHUNK 32
#define NCHUNK (D_DIM / CHUNK)   // 2
#define PFDIST 3
#define TPB   128
#define FULL  0xffffffffu

__device__ __forceinline__ void plane_stats(const float* __restrict__ pbase,
                                            int ym_off, int yp_off,
                                            int li_off, int ri_off, int lane,
                                            float4& xc, float4& mc, float4& mf)
{
    const float* __restrict__ r0 = pbase + ym_off;   // row y-1 (clamped)
    const float* __restrict__ r1 = pbase;            // row y
    const float* __restrict__ r2 = pbase + yp_off;   // row y+1 (clamped)

    float4 v0 = *(const float4*)r0;
    float4 v1 = *(const float4*)r1;
    float4 v2 = *(const float4*)r2;

    // edge-lane halo scalars (predicated; 1 wavefront each)
    float Lt_e, Lc_e, Rt_e, Rc_e;
    if (lane == 0) {
        Lt_e = fmaxf(r0[li_off], r2[li_off]);
        Lc_e = r1[li_off];
    }
    if (lane == 31) {
        Rt_e = fmaxf(r0[ri_off], r2[ri_off]);
        Rc_e = r1[ri_off];
    }

    // vertical max of top/bottom rows
    float4 t;
    t.x = fmaxf(v0.x, v2.x);
    t.y = fmaxf(v0.y, v2.y);
    t.z = fmaxf(v0.z, v2.z);
    t.w = fmaxf(v0.w, v2.w);

    float Lt_s = __shfl_up_sync(FULL,   t.w, 1);
    float Rt_s = __shfl_down_sync(FULL, t.x, 1);
    float Lc_s = __shfl_up_sync(FULL,   v1.w, 1);
    float Rc_s = __shfl_down_sync(FULL, v1.x, 1);

    float Lt = (lane == 0)  ? Lt_e : Lt_s;
    float Rt = (lane == 31) ? Rt_e : Rt_s;
    float Lc = (lane == 0)  ? Lc_e : Lc_s;
    float Rc = (lane == 31) ? Rc_e : Rc_s;

    // lr first: left/right neighbors of center row (exclude center)
    float4 lr;
    lr.x = fmaxf(Lc,   v1.y);
    lr.y = fmaxf(v1.x, v1.z);
    lr.z = fmaxf(v1.y, v1.w);
    lr.w = fmaxf(v1.z, Rc);

    // rb = hmax3(center row) = max(lr, center)
    float4 rb;
    rb.x = fmaxf(lr.x, v1.x);
    rb.y = fmaxf(lr.y, v1.y);
    rb.z = fmaxf(lr.z, v1.z);
    rb.w = fmaxf(lr.w, v1.w);

    // s = hmax3(t) via pairwise partials (7 ops)
    float px = fmaxf(t.x, t.y);
    float py = fmaxf(t.y, t.z);
    float pz = fmaxf(t.z, t.w);
    float4 s;
    s.x = fmaxf(Lt, px);
    s.y = fmaxf(px, t.z);
    s.z = fmaxf(py, t.w);
    s.w = fmaxf(pz, Rt);

    mf.x = fmaxf(s.x, rb.x);
    mf.y = fmaxf(s.y, rb.y);
    mf.z = fmaxf(s.z, rb.z);
    mf.w = fmaxf(s.w, rb.w);

    mc.x = fmaxf(s.x, lr.x);
    mc.y = fmaxf(s.y, lr.y);
    mc.z = fmaxf(s.z, lr.z);
    mc.w = fmaxf(s.w, lr.w);

    xc = v1;
}

__global__ __launch_bounds__(TPB, 8)
void nms3d_kernel(const float* __restrict__ in, float* __restrict__ out)
{
    const int tid  = blockIdx.x * TPB + threadIdx.x;
    const int lane = threadIdx.x & 31;

    const int x4    = tid & (W4 - 1);
    const int y     = (tid >> 6) & (H_DIM - 1);
    const int rest  = tid >> 14;
    const int chunk = rest & (NCHUNK - 1);
    const int bc    = rest >> 1;               // NCHUNK == 2

    const int d0 = chunk * CHUNK;

    const float* __restrict__ anchor =
        in + (size_t)bc * D_DIM * HW + (size_t)d0 * HW + y * W_DIM + 4 * x4;
    float* __restrict__ oanchor =
        out + (size_t)bc * D_DIM * HW + (size_t)d0 * HW + y * W_DIM + 4 * x4;

    const int ym_off = ((y > 0)         ? -W_DIM : 0);
    const int yp_off = ((y < H_DIM - 1) ?  W_DIM : 0);
    const int li_off = (x4 == 0)      ? 0 : -1;   // clamp == self at x edge
    const int ri_off = (x4 == W4 - 1) ? 3 : 4;

    // warm L2 for the first planes of this chunk (own row only; halo rows
    // arrive via the neighboring-y threads' prefetches)
    if ((lane & 7) == 0) {
        #pragma unroll
        for (int k = 0; k < PFDIST; ++k)
            if (d0 + k < D_DIM)
                asm volatile("prefetch.global.L2 [%0];" :: "l"(anchor + (size_t)k * HW));
    }

    float4 xc, mc, mf, mf_prev;
    {
        // stats of plane clamp(d0-1): for d0==0 this is plane 0 itself, whose
        // mf includes the center -> face plane suppressed (reference-exact).
        float4 txc, tmc;
        const float* prev = (d0 == 0) ? anchor : anchor - HW;
        plane_stats(prev,   ym_off, yp_off, li_off, ri_off, lane, txc, tmc, mf_prev);
        plane_stats(anchor, ym_off, yp_off, li_off, ri_off, lane, xc, mc, mf);
    }

    const float* pn = anchor + HW;              // plane d+1 (clamped at end)
    const float* pf = anchor + (size_t)PFDIST * HW;   // marching prefetch ptr
    const int dlast = D_DIM - 1;

    #pragma unroll 2
    for (int d = d0; d < d0 + CHUNK; ++d) {
        // prefetch own row of plane d+PFDIST into L2
        if ((lane & 7) == 0 && d + PFDIST < D_DIM)
            asm volatile("prefetch.global.L2 [%0];" :: "l"(pf));

        // stats of plane min(d+1, dlast); last plane recompute == current mf.
        float4 xcn, mcn, mfn;
        const float* psrc = (d < dlast) ? pn : pn - HW;
        plane_stats(psrc, ym_off, yp_off, li_off, ri_off, lane, xcn, mcn, mfn);

        float4 m, o;
        m.x = fmaxf(fmaxf(mf_prev.x, mc.x), mfn.x);
        m.y = fmaxf(fmaxf(mf_prev.y, mc.y), mfn.y);
        m.z = fmaxf(fmaxf(mf_prev.z, mc.z), mfn.z);
        m.w = fmaxf(fmaxf(mf_prev.w, mc.w), mfn.w);

        o.x = (xc.x > m.x) ? xc.x : 0.0f;
        o.y = (xc.y > m.y) ? xc.y : 0.0f;
        o.z = (xc.z > m.z) ? xc.z : 0.0f;
        o.w = (xc.w > m.w) ? xc.w : 0.0f;

        // streaming store: output never re-read, keep input resident in L2
        __stcs((float4*)oanchor, o);

        mf_prev = mf;
        xc = xcn; mc = mcn; mf = mfn;   // unroll 2 renames these, no MOVs
        pn += HW;
        pf += HW;
        oanchor += HW;
    }
}

extern "C" void kernel_launch(void* const* d_in, const int* in_sizes, int n_in,
                              void* d_out, int out_size)
{
    const float* x   = (const float*)d_in[0];
    float*       out = (float*)d_out;

    const int n  = in_sizes[0];
    const int bc = n / (D_DIM * HW);               // = 8 for the reference shape

    const int total   = bc * H_DIM * W4 * NCHUNK;  // thread per (bc,y,x4,chunk)
    const int blocks  = total / TPB;               // 2048 for the reference shape

    nms3d_kernel<<<blocks, TPB>>>(x, out);
}